// round 4
// baseline (speedup 1.0000x reference)
#include <cuda_runtime.h>

// ZoeDepth metric depth head, fused single kernel.
// Inputs (metadata order): x[4,128,192,192], prev_bin[4,64,96,96],
//   prev_bin_embedding[4,128,96,96], w1[128,128], b1[128], w2[32,128], b2[32]
// Output: concat(bin_new_centers[4,64,192,192], bin_centers[4,64,192,192])

namespace {
constexpr int Hc = 192, Wc = 192, SHc = 96, SWc = 96, Cc = 128, NB = 64, NA = 16;
constexpr int BLKT = 256;
constexpr float ALPHAc = 300.0f;

__device__ __forceinline__ unsigned long long pack2(float lo, float hi) {
    unsigned long long r;
    asm("mov.b64 %0, {%1, %2};" : "=l"(r) : "f"(lo), "f"(hi));
    return r;
}
__device__ __forceinline__ void unpack2(unsigned long long v, float& lo, float& hi) {
    asm("mov.b64 {%0, %1}, %2;" : "=f"(lo), "=f"(hi) : "l"(v));
}
// packed fp32x2 fma: d = a*b + d (elementwise on 2 floats)
__device__ __forceinline__ void fma2(unsigned long long& d, unsigned long long a, unsigned long long b) {
    asm("fma.rn.f32x2 %0, %1, %2, %3;" : "=l"(d) : "l"(a), "l"(b), "l"(d));
}
} // namespace

__global__ __launch_bounds__(BLKT, 1)
void zoe_head_kernel(const float* __restrict__ x,
                     const float* __restrict__ prev_bin,
                     const float* __restrict__ pe,
                     const float* __restrict__ w1,
                     const float* __restrict__ b1,
                     const float* __restrict__ w2,
                     const float* __restrict__ b2,
                     float* __restrict__ out,
                     int total_pixels, long long half_out)
{
    extern __shared__ float smem[];
    float* w1_s  = smem;                  // 16384 floats (64KB) — reused as arr_s later
    float* w2e_s = smem + 16384;          // 2048 floats: w2e_s[o*16+i] = w2[2i][o]
    float* b1_s  = smem + 16384 + 2048;   // 128 floats

    const int t = threadIdx.x;

    // ---- cooperative weight staging ----
    {
        const float4* src = (const float4*)w1;
        float4* dst = (float4*)w1_s;
#pragma unroll
        for (int i = 0; i < 16; i++) dst[t + i * BLKT] = src[t + i * BLKT];  // 4096 float4
#pragma unroll
        for (int i = 0; i < 8; i++) {
            int idx = t + i * BLKT;          // 0..2047
            int o = idx >> 4, a = idx & 15;
            w2e_s[idx] = w2[(2 * a) * Cc + o];
        }
        if (t < Cc) b1_s[t] = b1[t];
    }

    int p = blockIdx.x * BLKT + t;
    if (p >= total_pixels) p = total_pixels - 1;   // duplicate-safe clamp (same values written)

    const int bIdx = p / (Hc * Wc);
    const int rem  = p - bIdx * (Hc * Wc);
    const int yy   = rem / Wc;
    const int xx   = rem - yy * Wc;

    // align_corners bilinear coords (96 -> 192): scale = 95/191
    const float fscale = (float)(SHc - 1) / (float)(Hc - 1);
    const float fy = yy * fscale;
    const float fx = xx * fscale;
    const int y0 = (int)fy, x0 = (int)fx;
    const int y1 = min(y0 + 1, SHc - 1), x1 = min(x0 + 1, SWc - 1);
    const float wy = fy - (float)y0, wx = fx - (float)x0;
    const float w00 = (1.f - wy) * (1.f - wx);
    const float w01 = (1.f - wy) * wx;
    const float w10 = wy * (1.f - wx);
    const float w11 = wy * wx;
    const int i00 = y0 * SWc + x0, i01 = y0 * SWc + x1;
    const int i10 = y1 * SWc + x0, i11 = y1 * SWc + x1;

    // ---- gather v = x + bilinear(prev_bin_embedding), pack to f32x2 pairs ----
    unsigned long long vv[64];
    const float* xb  = x  + (long long)bIdx * Cc * Hc * Wc + rem;
    const float* peb = pe + (long long)bIdx * Cc * SHc * SWc;
#pragma unroll
    for (int j = 0; j < 64; j++) {
        const float* pc0 = peb + (2 * j) * (SHc * SWc);
        float pv0 = w00 * __ldg(pc0 + i00) + w01 * __ldg(pc0 + i01)
                  + w10 * __ldg(pc0 + i10) + w11 * __ldg(pc0 + i11);
        float v0 = __ldg(xb + (long long)(2 * j) * (Hc * Wc)) + pv0;
        const float* pc1 = peb + (2 * j + 1) * (SHc * SWc);
        float pv1 = w00 * __ldg(pc1 + i00) + w01 * __ldg(pc1 + i01)
                  + w10 * __ldg(pc1 + i10) + w11 * __ldg(pc1 + i11);
        float v1 = __ldg(xb + (long long)(2 * j + 1) * (Hc * Wc)) + pv1;
        vv[j] = pack2(v0, v1);
    }

    __syncthreads();   // weights staged

    // ---- fused matvec: h1 = relu(W1 v + b1); att += W2even * h1 ----
    unsigned long long att2[8];
#pragma unroll
    for (int j = 0; j < 8; j++) att2[j] = pack2(__ldg(b2 + 4 * j), __ldg(b2 + 4 * j + 2));

#pragma unroll 1
    for (int o = 0; o < Cc; o++) {
        const ulonglong2* row = (const ulonglong2*)(w1_s + o * Cc);
        unsigned long long accA = 0ull, accB = 0ull;   // two chains for ILP
#pragma unroll
        for (int q = 0; q < 32; q++) {
            ulonglong2 wq = row[q];                    // broadcast LDS.128
            fma2(accA, wq.x, vv[2 * q]);
            fma2(accB, wq.y, vv[2 * q + 1]);
        }
        float a0, a1, c0, c1;
        unpack2(accA, a0, a1);
        unpack2(accB, c0, c1);
        float h = (a0 + c0) + (a1 + c1) + b1_s[o];
        h = fmaxf(h, 0.0f);
        unsigned long long hh = pack2(h, h);
        const ulonglong2* w2row = (const ulonglong2*)(w2e_s + o * 16);
#pragma unroll
        for (int q = 0; q < 4; q++) {
            ulonglong2 wq = w2row[q];
            fma2(att2[2 * q], wq.x, hh);
            fma2(att2[2 * q + 1], wq.y, hh);
        }
    }

    float att[16];
#pragma unroll
    for (int j = 0; j < 8; j++) {
        float lo, hi;
        unpack2(att2[j], lo, hi);
        att[2 * j]     = fmaxf(lo, 0.f) + 0.001f;
        att[2 * j + 1] = fmaxf(hi, 0.f) + 0.001f;
    }

    __syncthreads();   // all threads done reading w1_s — safe to reuse as arr_s
    float* arr_s = w1_s;   // [64][BLKT] layout, conflict-free per-thread column

    // ---- attractor stage + first output ----
    const float* pbb = prev_bin + (long long)bIdx * NB * SHc * SWc;
    float* out1 = out + (long long)bIdx * NB * Hc * Wc + rem;
#pragma unroll 1
    for (int ch = 0; ch < NB; ch++) {
        const float* pc = pbb + ch * (SHc * SWc);
        float bc = w00 * __ldg(pc + i00) + w01 * __ldg(pc + i01)
                 + w10 * __ldg(pc + i10) + w11 * __ldg(pc + i11);
        float s = 0.f;
#pragma unroll
        for (int i = 0; i < NA; i++) {
            float dx = att[i] - bc;
            float den = fmaf(ALPHAc * dx, dx, 1.0f);
            s += __fdividef(dx, den);
        }
        float bn = bc + s * (1.0f / 16.0f);
        out1[(long long)ch * (Hc * Wc)] = bn;                 // bin_new_centers
        arr_s[ch * BLKT + t] = fmaf(bn, 9.999f, 0.001f);      // staged for sort
    }

    // ---- load into registers, bitonic sort 64, clip, second output ----
    float arr[64];
#pragma unroll
    for (int ch = 0; ch < 64; ch++) arr[ch] = arr_s[ch * BLKT + t];

#pragma unroll
    for (int k = 2; k <= 64; k <<= 1) {
#pragma unroll
        for (int j = k >> 1; j > 0; j >>= 1) {
#pragma unroll
            for (int i = 0; i < 64; i++) {
                int l = i ^ j;
                if (l > i) {
                    float a = arr[i], bv = arr[l];
                    float mn = fminf(a, bv), mx = fmaxf(a, bv);
                    bool up = ((i & k) == 0);
                    arr[i] = up ? mn : mx;
                    arr[l] = up ? mx : mn;
                }
            }
        }
    }

    float* out2 = out1 + half_out;
#pragma unroll
    for (int ch = 0; ch < 64; ch++) {
        out2[(long long)ch * (Hc * Wc)] = fminf(fmaxf(arr[ch], 0.001f), 10.0f);
    }
}

extern "C" void kernel_launch(void* const* d_in, const int* in_sizes, int n_in,
                              void* d_out, int out_size) {
    const float* x  = (const float*)d_in[0];
    const float* pb = (const float*)d_in[1];
    const float* pe = (const float*)d_in[2];
    const float* w1 = (const float*)d_in[3];
    const float* b1 = (const float*)d_in[4];
    const float* w2 = (const float*)d_in[5];
    const float* b2 = (const float*)d_in[6];
    float* out = (float*)d_out;

    const int total_pixels = in_sizes[0] / Cc;          // B*H*W = 147456
    const long long half_out = (long long)out_size / 2; // offset of bin_centers
    const int grid = (total_pixels + BLKT - 1) / BLKT;  // 576

    const size_t smem_bytes = (size_t)(16384 + 2048 + 128) * sizeof(float);  // 74240
    cudaFuncSetAttribute(zoe_head_kernel,
                         cudaFuncAttributeMaxDynamicSharedMemorySize,
                         (int)smem_bytes);

    zoe_head_kernel<<<grid, BLKT, smem_bytes>>>(x, pb, pe, w1, b1, w2, b2, out,
                                                total_pixels, half_out);
}

// round 5
// speedup vs baseline: 1.1881x; 1.1881x over previous
#include <cuda_runtime.h>

// ZoeDepth metric depth head, fused single kernel — split-K pair version.
// Two threads per pixel: lane 2k handles input channels 0..63, lane 2k+1 handles 64..127.
// Inputs: x[4,128,192,192], prev_bin[4,64,96,96], prev_bin_embedding[4,128,96,96],
//         w1[128,128], b1[128], w2[32,128], b2[32]
// Output: concat(bin_new_centers[4,64,192,192], bin_centers[4,64,192,192])

namespace {
constexpr int Hc = 192, Wc = 192, SHc = 96, SWc = 96, Cc = 128, NB = 64, NA = 16;
constexpr int BLK = 512, PIX = 256;          // 512 threads handle 256 pixels
constexpr float ALPHAc = 300.0f;

__device__ __forceinline__ unsigned long long pack2(float lo, float hi) {
    unsigned long long r;
    asm("mov.b64 %0, {%1, %2};" : "=l"(r) : "f"(lo), "f"(hi));
    return r;
}
__device__ __forceinline__ void unpack2(unsigned long long v, float& lo, float& hi) {
    asm("mov.b64 {%0, %1}, %2;" : "=f"(lo), "=f"(hi) : "l"(v));
}
// packed fp32x2 fma: d = a*b + d (elementwise on 2 floats)
__device__ __forceinline__ void fma2(unsigned long long& d, unsigned long long a, unsigned long long b) {
    asm("fma.rn.f32x2 %0, %1, %2, %3;" : "=l"(d) : "l"(a), "l"(b), "l"(d));
}
} // namespace

__global__ __launch_bounds__(BLK, 1)
void zoe_head_kernel(const float* __restrict__ x,
                     const float* __restrict__ prev_bin,
                     const float* __restrict__ pe,
                     const float* __restrict__ w1,
                     const float* __restrict__ b1,
                     const float* __restrict__ w2,
                     const float* __restrict__ b2,
                     float* __restrict__ out,
                     int total_pixels, long long half_out)
{
    extern __shared__ float smem[];
    float* w1p   = smem;                  // 16384 floats (64KB), permuted; reused as arr_s
    float* w2e_s = smem + 16384;          // 2048 floats: w2e_s[o*16+a] = w2[2a][o]
    float* b1_s  = smem + 16384 + 2048;   // 128 floats

    const int t = threadIdx.x;
    const int half = t & 1;               // which channel-half this thread owns
    const int HW = Hc * Wc, SHW = SHc * SWc;

    // ---- cooperative weight staging ----
    // w1p float4-index layout: o*32 + q*2 + hf  <-  w1 float4 (o*32 + hf*16 + q)
    // (pair's two 16B rows per step are adjacent -> conflict-free 2-line broadcast)
    {
        const float4* src = (const float4*)w1;
        float4* dst = (float4*)w1p;
#pragma unroll
        for (int i = 0; i < 8; i++) {
            int idx = t + i * BLK;        // 0..4095
            int o = idx >> 5, r = idx & 31, q = r >> 1, hf = r & 1;
            dst[idx] = src[o * 32 + hf * 16 + q];
        }
#pragma unroll
        for (int i = 0; i < 4; i++) {
            int idx = t + i * BLK;        // 0..2047
            int o = idx >> 4, a = idx & 15;
            w2e_s[idx] = w2[(2 * a) * Cc + o];
        }
        if (t < Cc) b1_s[t] = b1[t];
    }

    int p = blockIdx.x * PIX + (t >> 1);
    if (p >= total_pixels) p = total_pixels - 1;   // duplicate-safe clamp

    const int bIdx = p / HW;
    const int rem  = p - bIdx * HW;
    const int yy   = rem / Wc;
    const int xx   = rem - yy * Wc;

    // align_corners bilinear coords (96 -> 192)
    const float fscale = (float)(SHc - 1) / (float)(Hc - 1);
    const float fy = yy * fscale, fx = xx * fscale;
    const int y0 = (int)fy, x0 = (int)fx;
    const int y1 = min(y0 + 1, SHc - 1), x1 = min(x0 + 1, SWc - 1);
    const float wy = fy - (float)y0, wx = fx - (float)x0;
    const float w00 = (1.f - wy) * (1.f - wx);
    const float w01 = (1.f - wy) * wx;
    const float w10 = wy * (1.f - wx);
    const float w11 = wy * wx;
    const int i00 = y0 * SWc + x0, i01 = y0 * SWc + x1;
    const int i10 = y1 * SWc + x0, i11 = y1 * SWc + x1;

    // ---- gather this thread's 64 channels: v = x + bilinear(pe) ----
    unsigned long long vv[32];
    const float* xb  = x  + (long long)bIdx * Cc * HW + (long long)(half * 64) * HW + rem;
    const float* peb = pe + (long long)bIdx * Cc * SHW + (long long)(half * 64) * SHW;
#pragma unroll
    for (int j = 0; j < 32; j++) {
        const float* pc0 = peb + (2 * j) * SHW;
        float pv0 = w00 * __ldg(pc0 + i00) + w01 * __ldg(pc0 + i01)
                  + w10 * __ldg(pc0 + i10) + w11 * __ldg(pc0 + i11);
        float v0 = __ldg(xb + (long long)(2 * j) * HW) + pv0;
        const float* pc1 = peb + (2 * j + 1) * SHW;
        float pv1 = w00 * __ldg(pc1 + i00) + w01 * __ldg(pc1 + i01)
                  + w10 * __ldg(pc1 + i10) + w11 * __ldg(pc1 + i11);
        float v1 = __ldg(xb + (long long)(2 * j + 1) * HW) + pv1;
        vv[j] = pack2(v0, v1);
    }

    __syncthreads();   // weights staged

    // ---- split-K fused matvec ----
    // Per op-step both threads compute half-dots for outputs op and op+1.
    // Even thread keeps o=op, odd keeps o=op+1; one shfl.bfly combines halves.
    unsigned long long att2[8];
#pragma unroll
    for (int j = 0; j < 8; j++)
        att2[j] = half ? 0ull : pack2(__ldg(b2 + 4 * j), __ldg(b2 + 4 * j + 2));

#pragma unroll 1
    for (int op = 0; op < Cc; op += 2) {
        const ulonglong2* rE = (const ulonglong2*)w1p + op * 32 + half;
        const ulonglong2* rO = rE + 32;
        unsigned long long aE0 = 0ull, aE1 = 0ull, aO0 = 0ull, aO1 = 0ull;
#pragma unroll
        for (int q = 0; q < 16; q++) {
            ulonglong2 we = rE[2 * q];
            ulonglong2 wo = rO[2 * q];
            fma2(aE0, we.x, vv[2 * q]);
            fma2(aE1, we.y, vv[2 * q + 1]);
            fma2(aO0, wo.x, vv[2 * q]);
            fma2(aO1, wo.y, vv[2 * q + 1]);
        }
        float e0, e1, f0, f1, g0, g1, k0, k1;
        unpack2(aE0, e0, e1); unpack2(aE1, f0, f1);
        float pE = (e0 + f0) + (e1 + f1);          // partial of output op
        unpack2(aO0, g0, g1); unpack2(aO1, k0, k1);
        float pO = (g0 + k0) + (g1 + k1);          // partial of output op+1

        float u = half ? pE : pO;                  // send the partial the partner keeps
        float vPart = __shfl_xor_sync(0xffffffffu, u, 1);
        const int o = op + half;
        float h = (half ? pO : pE) + vPart + b1_s[o];
        h = fmaxf(h, 0.0f);
        unsigned long long hh = pack2(h, h);
        const ulonglong2* w2row = (const ulonglong2*)(w2e_s + o * 16);
#pragma unroll
        for (int q = 0; q < 4; q++) {
            ulonglong2 wq = w2row[q];
            fma2(att2[2 * q], wq.x, hh);
            fma2(att2[2 * q + 1], wq.y, hh);
        }
    }

    // combine att partials across the pair (even-o part + odd-o part)
    float att[16];
#pragma unroll
    for (int j = 0; j < 8; j++) {
        unsigned long long pv = __shfl_xor_sync(0xffffffffu, att2[j], 1);
        float a0, a1, c0, c1;
        unpack2(att2[j], a0, a1);
        unpack2(pv, c0, c1);
        att[2 * j]     = fmaxf(a0 + c0, 0.f) + 0.001f;
        att[2 * j + 1] = fmaxf(a1 + c1, 0.f) + 0.001f;
    }

    __syncthreads();          // all threads done reading w1p — reuse as sort staging
    float* arr_s = w1p;       // [64][PIX]

    // ---- attractor stage (32 bins per thread) + first output ----
    const float* pbb = prev_bin + (long long)bIdx * NB * SHW;
    float* out1 = out + (long long)bIdx * NB * HW + rem;
#pragma unroll 1
    for (int k = 0; k < 32; k++) {
        const int ch = half * 32 + k;
        const float* pc = pbb + ch * SHW;
        float bc = w00 * __ldg(pc + i00) + w01 * __ldg(pc + i01)
                 + w10 * __ldg(pc + i10) + w11 * __ldg(pc + i11);
        float s = 0.f;
#pragma unroll
        for (int i = 0; i < NA; i++) {
            float dx = att[i] - bc;
            float den = fmaf(ALPHAc * dx, dx, 1.0f);
            s += __fdividef(dx, den);
        }
        float bn = bc + s * (1.0f / 16.0f);
        out1[(long long)ch * HW] = bn;                    // bin_new_centers
        arr_s[ch * PIX + (t >> 1)] = fmaf(bn, 9.999f, 0.001f);
    }

    __syncthreads();

    // ---- sort phase: threads 0..255 each sort one pixel's 64 bins ----
    if (t < PIX) {
        int p2 = blockIdx.x * PIX + t;
        if (p2 >= total_pixels) p2 = total_pixels - 1;
        const int bIdx2 = p2 / HW;
        const int rem2  = p2 - bIdx2 * HW;

        float arr[64];
#pragma unroll
        for (int ch = 0; ch < 64; ch++) arr[ch] = arr_s[ch * PIX + t];

#pragma unroll
        for (int k = 2; k <= 64; k <<= 1) {
#pragma unroll
            for (int j = k >> 1; j > 0; j >>= 1) {
#pragma unroll
                for (int i = 0; i < 64; i++) {
                    int l = i ^ j;
                    if (l > i) {
                        float a = arr[i], bv = arr[l];
                        float mn = fminf(a, bv), mx = fmaxf(a, bv);
                        bool up = ((i & k) == 0);
                        arr[i] = up ? mn : mx;
                        arr[l] = up ? mx : mn;
                    }
                }
            }
        }

        float* out2 = out + half_out + (long long)bIdx2 * NB * HW + rem2;
#pragma unroll
        for (int ch = 0; ch < 64; ch++)
            out2[(long long)ch * HW] = fminf(fmaxf(arr[ch], 0.001f), 10.0f);
    }
}

extern "C" void kernel_launch(void* const* d_in, const int* in_sizes, int n_in,
                              void* d_out, int out_size) {
    const float* x  = (const float*)d_in[0];
    const float* pb = (const float*)d_in[1];
    const float* pe = (const float*)d_in[2];
    const float* w1 = (const float*)d_in[3];
    const float* b1 = (const float*)d_in[4];
    const float* w2 = (const float*)d_in[5];
    const float* b2 = (const float*)d_in[6];
    float* out = (float*)d_out;

    const int total_pixels = in_sizes[0] / Cc;          // B*H*W = 147456
    const long long half_out = (long long)out_size / 2;
    const int grid = (total_pixels + PIX - 1) / PIX;    // 576

    const size_t smem_bytes = (size_t)(16384 + 2048 + 128) * sizeof(float);  // 74240
    cudaFuncSetAttribute(zoe_head_kernel,
                         cudaFuncAttributeMaxDynamicSharedMemorySize,
                         (int)smem_bytes);

    zoe_head_kernel<<<grid, BLK, smem_bytes>>>(x, pb, pe, w1, b1, w2, b2, out,
                                               total_pixels, half_out);
}

// round 9
// speedup vs baseline: 1.3047x; 1.0981x over previous
#include <cuda_runtime.h>
#include <cstdint>

// ZoeDepth metric depth head — tensor-core version via portable mma.sync tf32
// (sm_80-level PTX: harness target is compute_103 without the 'a' suffix, so
//  tcgen05/.kind::tf32 are unavailable; mma.sync is not).
// Per CTA: 128 pixels. GEMM1: D1[128px,128] = V[128,128] @ W1^T  (tf32 MMA)
//          h = relu(D1+b1) -> smem ; GEMM2: att[128px,16] = h @ W2even^T
// Then attractor + per-pixel bitonic sort (proven scalar code).

namespace {
constexpr int Hc = 192, Wc = 192, SHc = 96, SWc = 96, Cc = 128, NB = 64, NA = 16;
constexpr int PIXC = 128, NTHR = 256;
constexpr float ALPHAc = 300.0f;
constexpr int LDP = 132;                      // padded row stride (floats), conflict-free

// smem layout (in floats)
constexpr int OFF_V   = 0;                    // 128*132 — V tile; reused as arr_s
constexpr int OFF_W1  = OFF_V  + 128 * LDP;   // 128*132 — W1; reused as h tile
constexpr int OFF_W2E = OFF_W1 + 128 * LDP;   // 16*132
constexpr int OFF_B1S = OFF_W2E + 16 * LDP;   // 128
constexpr int OFF_B2S = OFF_B1S + 128;        // 16
constexpr int OFF_ATT = OFF_B2S + 16;         // 128*16 (16B-aligned: checked)
constexpr int SMEM_FLOATS = OFF_ATT + PIXC * 16;
constexpr int SMEM_BYTES  = SMEM_FLOATS * 4;  // ~152 KB

__device__ __forceinline__ float rna_tf32(float x) {
    float r; asm("cvt.rna.tf32.f32 %0, %1;" : "=f"(r) : "f"(x)); return r;
}
__device__ __forceinline__ void mma_tf32(float* d,
                                         uint32_t a0, uint32_t a1, uint32_t a2, uint32_t a3,
                                         uint32_t b0, uint32_t b1) {
    asm volatile("mma.sync.aligned.m16n8k8.row.col.f32.tf32.tf32.f32 "
                 "{%0,%1,%2,%3}, {%4,%5,%6,%7}, {%8,%9}, {%0,%1,%2,%3};"
                 : "+f"(d[0]), "+f"(d[1]), "+f"(d[2]), "+f"(d[3])
                 : "r"(a0), "r"(a1), "r"(a2), "r"(a3), "r"(b0), "r"(b1));
}
} // namespace

__global__ __launch_bounds__(NTHR, 1)
void zoe_head_mma_kernel(const float* __restrict__ x,
                         const float* __restrict__ prev_bin,
                         const float* __restrict__ pe,
                         const float* __restrict__ w1,
                         const float* __restrict__ b1,
                         const float* __restrict__ w2,
                         const float* __restrict__ b2,
                         float* __restrict__ out,
                         int total_pixels, long long half_out)
{
    extern __shared__ float smem[];
    float* vS   = smem + OFF_V;
    float* w1S  = smem + OFF_W1;     // later reused as h tile
    float* w2eS = smem + OFF_W2E;
    float* b1S  = smem + OFF_B1S;
    float* b2S  = smem + OFF_B2S;
    float* attS = smem + OFF_ATT;

    const int t = threadIdx.x;
    const int wid = t >> 5, lid = t & 31;
    const int g = lid >> 2, tig = lid & 3;    // mma fragment coords
    const int HW = Hc * Wc, SHW = SHc * SWc;

    // ---- stage W1 / W2even / biases (rna -> tf32) ----
    {
        const float4* w1v = (const float4*)w1;
#pragma unroll
        for (int i = 0; i < 16; i++) {
            int idx4 = t + i * NTHR;           // 0..4095
            int o = idx4 >> 5, q = idx4 & 31;
            float4 v = w1v[idx4];
            v.x = rna_tf32(v.x); v.y = rna_tf32(v.y); v.z = rna_tf32(v.z); v.w = rna_tf32(v.w);
            *(float4*)&w1S[o * LDP + q * 4] = v;
        }
        const float4* w2v = (const float4*)w2;
#pragma unroll
        for (int i = 0; i < 2; i++) {
            int idx4 = t + i * NTHR;           // 0..511
            int n = idx4 >> 5, q = idx4 & 31;
            float4 v = w2v[(2 * n) * 32 + q];  // even output rows of w2
            v.x = rna_tf32(v.x); v.y = rna_tf32(v.y); v.z = rna_tf32(v.z); v.w = rna_tf32(v.w);
            *(float4*)&w2eS[n * LDP + q * 4] = v;
        }
        if (t < Cc) b1S[t] = b1[t];
        if (t < NA) b2S[t] = b2[2 * t];
    }

    // ---- pixel coords (2 threads per pixel for staging/attractor) ----
    const int pxl  = t >> 1;
    const int half = t & 1;
    int p = blockIdx.x * PIXC + pxl;
    if (p >= total_pixels) p = total_pixels - 1;
    const int bIdx = p / HW;
    const int rem  = p - bIdx * HW;
    const int yy = rem / Wc, xx = rem - yy * Wc;
    const float fscale = (float)(SHc - 1) / (float)(Hc - 1);
    const float fy = yy * fscale, fx = xx * fscale;
    const int y0 = (int)fy, x0 = (int)fx;
    const int y1 = min(y0 + 1, SHc - 1), x1 = min(x0 + 1, SWc - 1);
    const float wy = fy - (float)y0, wx = fx - (float)x0;
    const float w00 = (1.f - wy) * (1.f - wx), w01 = (1.f - wy) * wx;
    const float w10 = wy * (1.f - wx),          w11 = wy * wx;
    const int i00 = y0 * SWc + x0, i01 = y0 * SWc + x1;
    const int i10 = y1 * SWc + x0, i11 = y1 * SWc + x1;

    // ---- stage V tile: v = x + bilinear(pe), rna -> tf32 ----
    {
        const float* xb  = x  + (long long)bIdx * Cc * HW + (long long)(half * 64) * HW + rem;
        const float* peb = pe + (long long)bIdx * Cc * SHW + (long long)(half * 64) * SHW;
        float* vrow = vS + pxl * LDP + half * 64;
#pragma unroll
        for (int j4 = 0; j4 < 16; j4++) {
            float4 v;
            float* vp = (float*)&v;
#pragma unroll
            for (int u = 0; u < 4; u++) {
                int j = j4 * 4 + u;
                const float* pc = peb + j * SHW;
                float pv = w00 * __ldg(pc + i00) + w01 * __ldg(pc + i01)
                         + w10 * __ldg(pc + i10) + w11 * __ldg(pc + i11);
                vp[u] = rna_tf32(__ldg(xb + (long long)j * HW) + pv);
            }
            *(float4*)&vrow[j4 * 4] = v;
        }
    }
    __syncthreads();

    // ---- GEMM1: each warp owns 16 pixel rows, all 128 output cols ----
    const int rA0 = (wid * 16 + g) * LDP;
    const int rA1 = rA0 + 8 * LDP;
    float acc[16][4];
#pragma unroll
    for (int j = 0; j < 16; j++)
#pragma unroll
        for (int q = 0; q < 4; q++) acc[j][q] = 0.f;

#pragma unroll 4
    for (int k = 0; k < 16; k++) {
        const int kc = k * 8 + tig;
        uint32_t a0 = __float_as_uint(vS[rA0 + kc]);
        uint32_t a1 = __float_as_uint(vS[rA1 + kc]);
        uint32_t a2 = __float_as_uint(vS[rA0 + kc + 4]);
        uint32_t a3 = __float_as_uint(vS[rA1 + kc + 4]);
#pragma unroll
        for (int j = 0; j < 16; j++) {
            const int nb = (j * 8 + g) * LDP + kc;
            uint32_t b0 = __float_as_uint(w1S[nb]);
            uint32_t b1f = __float_as_uint(w1S[nb + 4]);
            mma_tf32(acc[j], a0, a1, a2, a3, b0, b1f);
        }
    }
    __syncthreads();   // all warps done reading w1S -> safe to overwrite with h

    // ---- epilogue 1: h = rna(relu(D1 + b1)) -> h tile (w1S region) ----
    {
        float* hS = w1S;
#pragma unroll
        for (int j = 0; j < 16; j++) {
            const int c0 = j * 8 + 2 * tig;
            float bb0 = b1S[c0], bb1 = b1S[c0 + 1];
            float2 h0, h1;
            h0.x = rna_tf32(fmaxf(acc[j][0] + bb0, 0.f));
            h0.y = rna_tf32(fmaxf(acc[j][1] + bb1, 0.f));
            h1.x = rna_tf32(fmaxf(acc[j][2] + bb0, 0.f));
            h1.y = rna_tf32(fmaxf(acc[j][3] + bb1, 0.f));
            *(float2*)&hS[rA0 + c0] = h0;
            *(float2*)&hS[rA1 + c0] = h1;
        }
    }
    __syncthreads();

    // ---- GEMM2: att[16 px rows][16] = h @ W2even^T ----
    {
        const float* hS = w1S;
        float acc2[2][4];
#pragma unroll
        for (int j = 0; j < 2; j++)
#pragma unroll
            for (int q = 0; q < 4; q++) acc2[j][q] = 0.f;
#pragma unroll
        for (int k = 0; k < 16; k++) {
            const int kc = k * 8 + tig;
            uint32_t a0 = __float_as_uint(hS[rA0 + kc]);
            uint32_t a1 = __float_as_uint(hS[rA1 + kc]);
            uint32_t a2 = __float_as_uint(hS[rA0 + kc + 4]);
            uint32_t a3 = __float_as_uint(hS[rA1 + kc + 4]);
#pragma unroll
            for (int j = 0; j < 2; j++) {
                const int nb = (j * 8 + g) * LDP + kc;
                uint32_t b0 = __float_as_uint(w2eS[nb]);
                uint32_t b1f = __float_as_uint(w2eS[nb + 4]);
                mma_tf32(acc2[j], a0, a1, a2, a3, b0, b1f);
            }
        }
        // att = relu(d + b2even) + 0.001 -> attS[pixel][16]
#pragma unroll
        for (int j = 0; j < 2; j++) {
            const int c0 = j * 8 + 2 * tig;
            float bb0 = b2S[c0], bb1 = b2S[c0 + 1];
            float2 v0, v1;
            v0.x = fmaxf(acc2[j][0] + bb0, 0.f) + 0.001f;
            v0.y = fmaxf(acc2[j][1] + bb1, 0.f) + 0.001f;
            v1.x = fmaxf(acc2[j][2] + bb0, 0.f) + 0.001f;
            v1.y = fmaxf(acc2[j][3] + bb1, 0.f) + 0.001f;
            *(float2*)&attS[(wid * 16 + g) * 16 + c0]     = v0;
            *(float2*)&attS[(wid * 16 + g + 8) * 16 + c0] = v1;
        }
    }
    __syncthreads();

    // ---- attractor stage (2 threads per pixel, 32 bins each) ----
    float att[16];
    {
        const float4* ap = (const float4*)&attS[pxl * 16];
#pragma unroll
        for (int q = 0; q < 4; q++) {
            float4 v = ap[q];
            att[4 * q] = v.x; att[4 * q + 1] = v.y; att[4 * q + 2] = v.z; att[4 * q + 3] = v.w;
        }
    }
    float* arr_s = vS;   // V tile dead — reuse as [64][PIXC]
    const float* pbb = prev_bin + (long long)bIdx * NB * SHW;
    float* out1 = out + (long long)bIdx * NB * HW + rem;
#pragma unroll 1
    for (int k = 0; k < 32; k++) {
        const int ch = half * 32 + k;
        const float* pc = pbb + ch * SHW;
        float bc = w00 * __ldg(pc + i00) + w01 * __ldg(pc + i01)
                 + w10 * __ldg(pc + i10) + w11 * __ldg(pc + i11);
        float s = 0.f;
#pragma unroll
        for (int i = 0; i < NA; i++) {
            float dx = att[i] - bc;
            float den = fmaf(ALPHAc * dx, dx, 1.0f);
            s += __fdividef(dx, den);
        }
        float bn = bc + s * (1.0f / 16.0f);
        out1[(long long)ch * HW] = bn;
        arr_s[ch * PIXC + pxl] = fmaf(bn, 9.999f, 0.001f);
    }
    __syncthreads();

    // ---- sort phase: threads 0..127 each sort one pixel ----
    if (t < PIXC) {
        int p2 = blockIdx.x * PIXC + t;
        if (p2 >= total_pixels) p2 = total_pixels - 1;
        const int bIdx2 = p2 / HW;
        const int rem2  = p2 - bIdx2 * HW;
        float arr[64];
#pragma unroll
        for (int ch = 0; ch < 64; ch++) arr[ch] = arr_s[ch * PIXC + t];
#pragma unroll
        for (int k = 2; k <= 64; k <<= 1) {
#pragma unroll
            for (int j = k >> 1; j > 0; j >>= 1) {
#pragma unroll
                for (int i = 0; i < 64; i++) {
                    int l = i ^ j;
                    if (l > i) {
                        float a = arr[i], bv = arr[l];
                        float mn = fminf(a, bv), mx = fmaxf(a, bv);
                        bool up = ((i & k) == 0);
                        arr[i] = up ? mn : mx;
                        arr[l] = up ? mx : mn;
                    }
                }
            }
        }
        float* out2 = out + half_out + (long long)bIdx2 * NB * HW + rem2;
#pragma unroll
        for (int ch = 0; ch < 64; ch++)
            out2[(long long)ch * HW] = fminf(fmaxf(arr[ch], 0.001f), 10.0f);
    }
}

extern "C" void kernel_launch(void* const* d_in, const int* in_sizes, int n_in,
                              void* d_out, int out_size) {
    const float* x  = (const float*)d_in[0];
    const float* pb = (const float*)d_in[1];
    const float* pe = (const float*)d_in[2];
    const float* w1 = (const float*)d_in[3];
    const float* b1 = (const float*)d_in[4];
    const float* w2 = (const float*)d_in[5];
    const float* b2 = (const float*)d_in[6];
    float* out = (float*)d_out;

    const int total_pixels = in_sizes[0] / Cc;            // 147456
    const long long half_out = (long long)out_size / 2;
    const int grid = (total_pixels + PIXC - 1) / PIXC;    // 1152

    cudaFuncSetAttribute(zoe_head_mma_kernel,
                         cudaFuncAttributeMaxDynamicSharedMemorySize, SMEM_BYTES);

    zoe_head_mma_kernel<<<grid, NTHR, SMEM_BYTES>>>(x, pb, pe, w1, b1, w2, b2, out,
                                                    total_pixels, half_out);
}

// round 10
// speedup vs baseline: 1.8569x; 1.4233x over previous
#include <cuda_runtime.h>
#include <cstdint>

// ZoeDepth metric depth head — tf32 mma.sync, 512-thread CTA (16 warps).
// Per CTA: 128 pixels. GEMM1: D1[128,128] = V @ W1^T (each warp: 16 rows x 64 cols)
// h = relu(D1+b1) -> smem ; GEMM2: att[128,16] = h @ W2even^T (warp: 16 rows x 8 cols)
// Attractor: 4 threads/pixel (16 bins each). Sort: threads 0..127, bitonic-64.

namespace {
constexpr int Hc = 192, Wc = 192, SHc = 96, SWc = 96, Cc = 128, NB = 64, NA = 16;
constexpr int PIXC = 128, NTHR = 512;
constexpr float ALPHAc = 300.0f;
constexpr int LDP = 132;                      // padded row stride (floats), conflict-free
constexpr int PIXP = 129;                     // sort-staging stride, conflict-free

// smem layout (in floats)
constexpr int OFF_V   = 0;                    // 128*132 — V tile; reused as arr_s [64][129]
constexpr int OFF_W1  = OFF_V  + 128 * LDP;   // 128*132 — W1; reused as h tile
constexpr int OFF_W2E = OFF_W1 + 128 * LDP;   // 16*132
constexpr int OFF_B1S = OFF_W2E + 16 * LDP;   // 128
constexpr int OFF_B2S = OFF_B1S + 128;        // 16
constexpr int OFF_ATT = OFF_B2S + 16;         // 128*16 (byte offset 144192, 16B aligned)
constexpr int SMEM_FLOATS = OFF_ATT + PIXC * 16;
constexpr int SMEM_BYTES  = SMEM_FLOATS * 4;  // ~152 KB

__device__ __forceinline__ float rna_tf32(float x) {
    float r; asm("cvt.rna.tf32.f32 %0, %1;" : "=f"(r) : "f"(x)); return r;
}
__device__ __forceinline__ void mma_tf32(float* d,
                                         uint32_t a0, uint32_t a1, uint32_t a2, uint32_t a3,
                                         uint32_t b0, uint32_t b1) {
    asm volatile("mma.sync.aligned.m16n8k8.row.col.f32.tf32.tf32.f32 "
                 "{%0,%1,%2,%3}, {%4,%5,%6,%7}, {%8,%9}, {%0,%1,%2,%3};"
                 : "+f"(d[0]), "+f"(d[1]), "+f"(d[2]), "+f"(d[3])
                 : "r"(a0), "r"(a1), "r"(a2), "r"(a3), "r"(b0), "r"(b1));
}
} // namespace

__global__ __launch_bounds__(NTHR, 1)
void zoe_head_mma_kernel(const float* __restrict__ x,
                         const float* __restrict__ prev_bin,
                         const float* __restrict__ pe,
                         const float* __restrict__ w1,
                         const float* __restrict__ b1,
                         const float* __restrict__ w2,
                         const float* __restrict__ b2,
                         float* __restrict__ out,
                         int total_pixels, long long half_out)
{
    extern __shared__ float smem[];
    float* vS   = smem + OFF_V;
    float* w1S  = smem + OFF_W1;     // later reused as h tile
    float* w2eS = smem + OFF_W2E;
    float* b1S  = smem + OFF_B1S;
    float* b2S  = smem + OFF_B2S;
    float* attS = smem + OFF_ATT;

    const int t = threadIdx.x;
    const int wid = t >> 5, lid = t & 31;
    const int g = lid >> 2, tig = lid & 3;    // mma fragment coords
    const int HW = Hc * Wc, SHW = SHc * SWc;

    // ---- stage W1 / W2even / biases (rna -> tf32) ----
    {
        const float4* w1v = (const float4*)w1;
#pragma unroll
        for (int i = 0; i < 8; i++) {
            int idx4 = t + i * NTHR;           // 0..4095
            int o = idx4 >> 5, q = idx4 & 31;
            float4 v = w1v[idx4];
            v.x = rna_tf32(v.x); v.y = rna_tf32(v.y); v.z = rna_tf32(v.z); v.w = rna_tf32(v.w);
            *(float4*)&w1S[o * LDP + q * 4] = v;
        }
        if (t < 512) {
            int n = t >> 5, q = t & 31;
            float4 v = ((const float4*)w2)[(2 * n) * 32 + q];  // even output rows
            v.x = rna_tf32(v.x); v.y = rna_tf32(v.y); v.z = rna_tf32(v.z); v.w = rna_tf32(v.w);
            *(float4*)&w2eS[n * LDP + q * 4] = v;
        }
        if (t < Cc) b1S[t] = b1[t];
        if (t < NA) b2S[t] = b2[2 * t];
    }

    // ---- pixel coords (4 threads per pixel for staging/attractor) ----
    const int pxl = t >> 2;
    const int q4  = t & 3;
    int p = blockIdx.x * PIXC + pxl;
    if (p >= total_pixels) p = total_pixels - 1;
    const int bIdx = p / HW;
    const int rem  = p - bIdx * HW;
    const int yy = rem / Wc, xx = rem - yy * Wc;
    const float fscale = (float)(SHc - 1) / (float)(Hc - 1);
    const float fy = yy * fscale, fx = xx * fscale;
    const int y0 = (int)fy, x0 = (int)fx;
    const int y1 = min(y0 + 1, SHc - 1), x1 = min(x0 + 1, SWc - 1);
    const float wy = fy - (float)y0, wx = fx - (float)x0;
    const float w00 = (1.f - wy) * (1.f - wx), w01 = (1.f - wy) * wx;
    const float w10 = wy * (1.f - wx),          w11 = wy * wx;
    const int i00 = y0 * SWc + x0, i01 = y0 * SWc + x1;
    const int i10 = y1 * SWc + x0, i11 = y1 * SWc + x1;

    // ---- stage V tile: v = x + bilinear(pe), rna -> tf32 (32 channels/thread) ----
    {
        const int chb = q4 * 32;
        const float* xb  = x  + (long long)bIdx * Cc * HW + (long long)chb * HW + rem;
        const float* peb = pe + (long long)bIdx * Cc * SHW + (long long)chb * SHW;
        float* vrow = vS + pxl * LDP + chb;
#pragma unroll
        for (int j4 = 0; j4 < 8; j4++) {
            float4 v;
            float* vp = (float*)&v;
#pragma unroll
            for (int u = 0; u < 4; u++) {
                int j = j4 * 4 + u;
                const float* pc = peb + j * SHW;
                float pv = w00 * __ldg(pc + i00) + w01 * __ldg(pc + i01)
                         + w10 * __ldg(pc + i10) + w11 * __ldg(pc + i11);
                vp[u] = rna_tf32(__ldg(xb + (long long)j * HW) + pv);
            }
            *(float4*)&vrow[j4 * 4] = v;
        }
    }
    __syncthreads();

    // ---- GEMM1: warp = (row-group rg, col-half ch2); 16 rows x 64 cols ----
    const int rg  = wid >> 1;
    const int ch2 = wid & 1;
    const int rA0 = (rg * 16 + g) * LDP;
    const int rA1 = rA0 + 8 * LDP;
    float acc[8][4];
#pragma unroll
    for (int j = 0; j < 8; j++)
#pragma unroll
        for (int qq = 0; qq < 4; qq++) acc[j][qq] = 0.f;

#pragma unroll 4
    for (int k = 0; k < 16; k++) {
        const int kc = k * 8 + tig;
        uint32_t a0 = __float_as_uint(vS[rA0 + kc]);
        uint32_t a1 = __float_as_uint(vS[rA1 + kc]);
        uint32_t a2 = __float_as_uint(vS[rA0 + kc + 4]);
        uint32_t a3 = __float_as_uint(vS[rA1 + kc + 4]);
#pragma unroll
        for (int j = 0; j < 8; j++) {
            const int nb = (ch2 * 64 + j * 8 + g) * LDP + kc;
            uint32_t b0 = __float_as_uint(w1S[nb]);
            uint32_t b1f = __float_as_uint(w1S[nb + 4]);
            mma_tf32(acc[j], a0, a1, a2, a3, b0, b1f);
        }
    }
    __syncthreads();   // all warps done reading w1S -> safe to overwrite with h

    // ---- epilogue 1: h = rna(relu(D1 + b1)) -> h tile (w1S region) ----
    {
        float* hS = w1S;
#pragma unroll
        for (int j = 0; j < 8; j++) {
            const int c0 = ch2 * 64 + j * 8 + 2 * tig;
            float bb0 = b1S[c0], bb1 = b1S[c0 + 1];
            float2 h0, h1;
            h0.x = rna_tf32(fmaxf(acc[j][0] + bb0, 0.f));
            h0.y = rna_tf32(fmaxf(acc[j][1] + bb1, 0.f));
            h1.x = rna_tf32(fmaxf(acc[j][2] + bb0, 0.f));
            h1.y = rna_tf32(fmaxf(acc[j][3] + bb1, 0.f));
            *(float2*)&hS[rA0 + c0] = h0;
            *(float2*)&hS[rA1 + c0] = h1;
        }
    }
    __syncthreads();

    // ---- GEMM2: warp = (row-group, n-tile); att[16 rows][8 cols] ----
    {
        const float* hS = w1S;
        const int j2 = ch2;                    // n-tile 0 or 1
        float acc2[4] = {0.f, 0.f, 0.f, 0.f};
#pragma unroll
        for (int k = 0; k < 16; k++) {
            const int kc = k * 8 + tig;
            uint32_t a0 = __float_as_uint(hS[rA0 + kc]);
            uint32_t a1 = __float_as_uint(hS[rA1 + kc]);
            uint32_t a2 = __float_as_uint(hS[rA0 + kc + 4]);
            uint32_t a3 = __float_as_uint(hS[rA1 + kc + 4]);
            const int nb = (j2 * 8 + g) * LDP + kc;
            uint32_t b0 = __float_as_uint(w2eS[nb]);
            uint32_t b1f = __float_as_uint(w2eS[nb + 4]);
            mma_tf32(acc2, a0, a1, a2, a3, b0, b1f);
        }
        // att = relu(d + b2even) + 0.001 -> attS[pixel][16]
        const int c0 = j2 * 8 + 2 * tig;
        float bb0 = b2S[c0], bb1 = b2S[c0 + 1];
        float2 v0, v1;
        v0.x = fmaxf(acc2[0] + bb0, 0.f) + 0.001f;
        v0.y = fmaxf(acc2[1] + bb1, 0.f) + 0.001f;
        v1.x = fmaxf(acc2[2] + bb0, 0.f) + 0.001f;
        v1.y = fmaxf(acc2[3] + bb1, 0.f) + 0.001f;
        *(float2*)&attS[(rg * 16 + g) * 16 + c0]     = v0;
        *(float2*)&attS[(rg * 16 + g + 8) * 16 + c0] = v1;
    }
    __syncthreads();

    // ---- attractor stage (4 threads per pixel, 16 bins each) ----
    float att[16];
    {
        const float4* ap = (const float4*)&attS[pxl * 16];
#pragma unroll
        for (int qq = 0; qq < 4; qq++) {
            float4 v = ap[qq];
            att[4 * qq] = v.x; att[4 * qq + 1] = v.y; att[4 * qq + 2] = v.z; att[4 * qq + 3] = v.w;
        }
    }
    float* arr_s = vS;   // V tile dead — reuse as [64][PIXP]
    const float* pbb = prev_bin + (long long)bIdx * NB * SHW;
    float* out1 = out + (long long)bIdx * NB * HW + rem;
#pragma unroll 2
    for (int k = 0; k < 16; k++) {
        const int ch = q4 * 16 + k;
        const float* pc = pbb + ch * SHW;
        float bc = w00 * __ldg(pc + i00) + w01 * __ldg(pc + i01)
                 + w10 * __ldg(pc + i10) + w11 * __ldg(pc + i11);
        float s = 0.f;
#pragma unroll
        for (int i = 0; i < NA; i++) {
            float dx = att[i] - bc;
            float den = fmaf(ALPHAc * dx, dx, 1.0f);
            s += __fdividef(dx, den);
        }
        float bn = bc + s * (1.0f / 16.0f);
        out1[(long long)ch * HW] = bn;
        arr_s[ch * PIXP + pxl] = fmaf(bn, 9.999f, 0.001f);
    }
    __syncthreads();

    // ---- sort phase: threads 0..127 each sort one pixel ----
    if (t < PIXC) {
        int p2 = blockIdx.x * PIXC + t;
        if (p2 >= total_pixels) p2 = total_pixels - 1;
        const int bIdx2 = p2 / HW;
        const int rem2  = p2 - bIdx2 * HW;
        float arr[64];
#pragma unroll
        for (int ch = 0; ch < 64; ch++) arr[ch] = arr_s[ch * PIXP + t];
#pragma unroll
        for (int k = 2; k <= 64; k <<= 1) {
#pragma unroll
            for (int j = k >> 1; j > 0; j >>= 1) {
#pragma unroll
                for (int i = 0; i < 64; i++) {
                    int l = i ^ j;
                    if (l > i) {
                        float a = arr[i], bv = arr[l];
                        float mn = fminf(a, bv), mx = fmaxf(a, bv);
                        bool up = ((i & k) == 0);
                        arr[i] = up ? mn : mx;
                        arr[l] = up ? mx : mn;
                    }
                }
            }
        }
        float* out2 = out + half_out + (long long)bIdx2 * NB * HW + rem2;
#pragma unroll
        for (int ch = 0; ch < 64; ch++)
            out2[(long long)ch * HW] = fminf(fmaxf(arr[ch], 0.001f), 10.0f);
    }
}

extern "C" void kernel_launch(void* const* d_in, const int* in_sizes, int n_in,
                              void* d_out, int out_size) {
    const float* x  = (const float*)d_in[0];
    const float* pb = (const float*)d_in[1];
    const float* pe = (const float*)d_in[2];
    const float* w1 = (const float*)d_in[3];
    const float* b1 = (const float*)d_in[4];
    const float* w2 = (const float*)d_in[5];
    const float* b2 = (const float*)d_in[6];
    float* out = (float*)d_out;

    const int total_pixels = in_sizes[0] / Cc;            // 147456
    const long long half_out = (long long)out_size / 2;
    const int grid = (total_pixels + PIXC - 1) / PIXC;    // 1152

    cudaFuncSetAttribute(zoe_head_mma_kernel,
                         cudaFuncAttributeMaxDynamicSharedMemorySize, SMEM_BYTES);

    zoe_head_mma_kernel<<<grid, NTHR, SMEM_BYTES>>>(x, pb, pe, w1, b1, w2, b2, out,
                                                    total_pixels, half_out);
}